// round 4
// baseline (speedup 1.0000x reference)
#include <cuda_runtime.h>

#define F 96
#define C4 24               // float4 chunks per row
#define CAPN 50240          // node capacity (N = 50000)
#define CAPE 1000000        // edge capacity (E = 899999)
#define THRESH 2048         // rows longer than this -> heavy kernel
#define FULLM 0xffffffffu

// ---- scratch (__device__ globals; zero-initialized at load) ----
__device__ int    g_degi  [CAPN];          // must be zero before deg_kernel:
                                           // static zero-init; scan re-zeroes it
__device__ float  g_dinv  [CAPN];
__device__ int    g_rowptr[CAPN + 8];
__device__ int    g_cursor[CAPN];
__device__ float2 g_en    [CAPE];          // (src bits, norm) per CSR slot
__device__ int    g_heavy [64];
__device__ int    g_nheavy;
__device__ float4 g_agg4  [CAPN * C4];     // aggregated features
__device__ float  g_h1    [CAPN * F];      // relu(xagg @ W1 + b1)

// ---- f32x2 packed helpers ----
__device__ __forceinline__ void fma2(unsigned long long& a,
                                     unsigned long long v,
                                     unsigned long long m) {
    asm volatile("fma.rn.f32x2 %0, %1, %2, %0;" : "+l"(a) : "l"(v), "l"(m));
}
__device__ __forceinline__ unsigned long long dup2(float x) {
    unsigned long long r;
    asm("mov.b64 %0, {%1, %1};" : "=l"(r) : "r"(__float_as_uint(x)));
    return r;
}

// ---------------------------------------------------------------------------
// (launch 0) degree by dst; warp-aggregated for contiguous hub edges
// ---------------------------------------------------------------------------
__global__ void deg_kernel(const int* __restrict__ dst, int E) {
    int e = blockIdx.x * blockDim.x + threadIdx.x;
    bool valid = e < E;
    int d = valid ? dst[e] : -1;
    int d0 = __shfl_sync(FULLM, d, 0);
    unsigned bal = __ballot_sync(FULLM, valid && d == d0);
    if (bal == FULLM) {
        if ((threadIdx.x & 31) == 0) atomicAdd(&g_degi[d0], 32);
    } else if (valid) {
        atomicAdd(&g_degi[d], 1);
    }
}

// ---------------------------------------------------------------------------
// (launch 1) single-block: scan degi -> rowptr/cursor, dinv, heavy list,
// and re-zero degi for the next replay
// ---------------------------------------------------------------------------
__global__ void scan_kernel(int N, int E) {
    __shared__ int s[1024];
    __shared__ int s_nh;
    const int T = 1024, t = threadIdx.x;
    if (t == 0) s_nh = 0;
    int chunk = (N + T - 1) / T;
    int beg = t * chunk, end = min(beg + chunk, N);
    int sum = 0;
    for (int i = beg; i < end; i++) sum += g_degi[i];
    s[t] = sum;
    __syncthreads();
    for (int off = 1; off < T; off <<= 1) {
        int v = (t >= off) ? s[t - off] : 0;
        __syncthreads();
        if (t >= off) s[t] += v;
        __syncthreads();
    }
    int run = (t == 0) ? 0 : s[t - 1];
    for (int i = beg; i < end; i++) {
        int dg = g_degi[i];
        g_rowptr[i] = run;
        g_cursor[i] = run;
        run += dg;
        float fd = (float)dg;
        g_dinv[i] = dg > 0 ? rsqrtf(fmaxf(fd, 1.f)) : 0.f;
        if (dg > THRESH) {
            int k = atomicAdd(&s_nh, 1);
            if (k < 64) g_heavy[k] = i;
        }
        g_degi[i] = 0;                      // reset for next replay
    }
    __syncthreads();
    if (t == 0) {
        g_nheavy = min(s_nh, 64);
        for (int i = 0; i <= 6; i++) g_rowptr[N + i] = E;  // tail padding
    }
}

// ---------------------------------------------------------------------------
// (launch 2) CSR fill: write (src, norm) pairs; warp-aggregated hub cursor
// ---------------------------------------------------------------------------
__global__ void fill_kernel(const int* __restrict__ src,
                            const int* __restrict__ dst, int E) {
    int e = blockIdx.x * blockDim.x + threadIdx.x;
    bool valid = e < E;
    int s = 0, d = -1;
    float nm = 0.f;
    if (valid) { s = src[e]; d = dst[e]; nm = g_dinv[s] * g_dinv[d]; }
    int d0 = __shfl_sync(FULLM, d, 0);
    unsigned bal = __ballot_sync(FULLM, valid && d == d0);
    int pos = 0;
    if (bal == FULLM) {
        if ((threadIdx.x & 31) == 0) pos = atomicAdd(&g_cursor[d0], 32);
        pos = __shfl_sync(FULLM, pos, 0) + (threadIdx.x & 31);
    } else if (valid) {
        pos = atomicAdd(&g_cursor[d], 1);
    }
    if (valid) g_en[pos] = make_float2(__int_as_float(s), nm);
}

// ---------------------------------------------------------------------------
// Gather: 4 nodes per 96-thread block; 24 threads per node, one float4
// chunk per thread. Edge (src,norm) staged in smem tiles of 64/node.
// Inner loop: LDS.64 + LDG.128 + 2 x fma.rn.f32x2 per edge per thread.
// Heavy rows (hub) write zeros here; heavy_kernel accumulates them.
// ---------------------------------------------------------------------------
#define TILE 64
__global__ void __launch_bounds__(96, 8) gather_kernel(
        const float* __restrict__ feat, int N) {
    const int t = threadIdx.x;
    const int slot = t / C4;            // 0..3
    const int c = t % C4;               // float4 chunk 0..23
    __shared__ int    sinfo[5];         // rowptr[n0 .. n0+4]
    __shared__ int    scnt [4];         // masked edge counts
    __shared__ float2 sen  [4 * TILE];

    const int n0 = blockIdx.x * 4;
    if (t < 5) sinfo[t] = g_rowptr[n0 + t];
    __syncthreads();

    const int beg = sinfo[slot];
    int cnt = sinfo[slot + 1] - beg;
    if (cnt > THRESH) cnt = 0;          // heavy -> handled by heavy_kernel
    if (c == 0) scnt[slot] = cnt;
    __syncthreads();
    int maxc = max(max(scnt[0], scnt[1]), max(scnt[2], scnt[3]));

    const ulonglong2* __restrict__ f2 = (const ulonglong2*)feat;
    unsigned long long a0 = 0ull, a1 = 0ull;

    for (int tb = 0; tb * TILE < maxc; tb++) {
        __syncthreads();
        for (int idx = t; idx < 4 * TILE; idx += 96) {
            int s2 = idx >> 6, o = idx & (TILE - 1);
            int off = tb * TILE + o;
            if (off < scnt[s2]) sen[idx] = g_en[sinfo[s2] + off];
        }
        __syncthreads();
        int rem = min(TILE, cnt - tb * TILE);
        if (rem > 0) {
            const float2* me = sen + slot * TILE;
            int j = 0;
            for (; j + 4 <= rem; j += 4) {
                float2 e0 = me[j], e1 = me[j + 1], e2 = me[j + 2], e3 = me[j + 3];
                ulonglong2 v0 = __ldg(f2 + (size_t)__float_as_int(e0.x) * C4 + c);
                ulonglong2 v1 = __ldg(f2 + (size_t)__float_as_int(e1.x) * C4 + c);
                ulonglong2 v2 = __ldg(f2 + (size_t)__float_as_int(e2.x) * C4 + c);
                ulonglong2 v3 = __ldg(f2 + (size_t)__float_as_int(e3.x) * C4 + c);
                unsigned long long m0 = dup2(e0.y), m1 = dup2(e1.y);
                unsigned long long m2 = dup2(e2.y), m3 = dup2(e3.y);
                fma2(a0, v0.x, m0); fma2(a1, v0.y, m0);
                fma2(a0, v1.x, m1); fma2(a1, v1.y, m1);
                fma2(a0, v2.x, m2); fma2(a1, v2.y, m2);
                fma2(a0, v3.x, m3); fma2(a1, v3.y, m3);
            }
            for (; j < rem; j++) {
                float2 e0 = me[j];
                ulonglong2 v0 = __ldg(f2 + (size_t)__float_as_int(e0.x) * C4 + c);
                unsigned long long m0 = dup2(e0.y);
                fma2(a0, v0.x, m0); fma2(a1, v0.y, m0);
            }
        }
    }

    int n = n0 + slot;
    if (n < N) {
        float2 lo = *(float2*)&a0, hi = *(float2*)&a1;
        g_agg4[(size_t)n * C4 + c] = make_float4(lo.x, lo.y, hi.x, hi.y);
    }
}

// heavy rows (hub): grid-stride 256-edge tiles, same inner loop, atomic finish
__global__ void __launch_bounds__(96, 8) heavy_kernel(
        const float* __restrict__ feat) {
    int nh = g_nheavy;
    if (nh <= 0) return;
    const int t = threadIdx.x;
    const int slot = t / C4;
    const int c = t % C4;
    __shared__ float2 sen[4 * TILE];
    __shared__ float4 red[96];
    const ulonglong2* __restrict__ f2 = (const ulonglong2*)feat;

    for (int h = 0; h < nh; h++) {
        int node = g_heavy[h];
        int beg = g_rowptr[node];
        int cnt = g_rowptr[node + 1] - beg;
        int nt = (cnt + 255) / 256;
        unsigned long long a0 = 0ull, a1 = 0ull;

        for (int bt = blockIdx.x; bt < nt; bt += gridDim.x) {
            int base = bt * 256;
            __syncthreads();
            for (int idx = t; idx < 4 * TILE; idx += 96) {
                int off = base + idx;
                if (off < cnt) sen[idx] = g_en[beg + off];
            }
            __syncthreads();
            int rem = min(TILE, cnt - base - slot * TILE);
            if (rem > 0) {
                const float2* me = sen + slot * TILE;
                int j = 0;
                for (; j + 4 <= rem; j += 4) {
                    float2 e0 = me[j], e1 = me[j + 1], e2 = me[j + 2], e3 = me[j + 3];
                    ulonglong2 v0 = __ldg(f2 + (size_t)__float_as_int(e0.x) * C4 + c);
                    ulonglong2 v1 = __ldg(f2 + (size_t)__float_as_int(e1.x) * C4 + c);
                    ulonglong2 v2 = __ldg(f2 + (size_t)__float_as_int(e2.x) * C4 + c);
                    ulonglong2 v3 = __ldg(f2 + (size_t)__float_as_int(e3.x) * C4 + c);
                    unsigned long long m0 = dup2(e0.y), m1 = dup2(e1.y);
                    unsigned long long m2 = dup2(e2.y), m3 = dup2(e3.y);
                    fma2(a0, v0.x, m0); fma2(a1, v0.y, m0);
                    fma2(a0, v1.x, m1); fma2(a1, v1.y, m1);
                    fma2(a0, v2.x, m2); fma2(a1, v2.y, m2);
                    fma2(a0, v3.x, m3); fma2(a1, v3.y, m3);
                }
                for (; j < rem; j++) {
                    float2 e0 = me[j];
                    ulonglong2 v0 = __ldg(f2 + (size_t)__float_as_int(e0.x) * C4 + c);
                    unsigned long long m0 = dup2(e0.y);
                    fma2(a0, v0.x, m0); fma2(a1, v0.y, m0);
                }
            }
        }
        // cross-slot reduce, then atomic accumulate into g_agg4[node]
        __syncthreads();
        float2 lo = *(float2*)&a0, hi = *(float2*)&a1;
        red[t] = make_float4(lo.x, lo.y, hi.x, hi.y);
        __syncthreads();
        if (t < 24) {
            float4 r0 = red[t], r1 = red[t + 24], r2 = red[t + 48], r3 = red[t + 72];
            float rx = r0.x + r1.x + r2.x + r3.x;
            float ry = r0.y + r1.y + r2.y + r3.y;
            float rz = r0.z + r1.z + r2.z + r3.z;
            float rw = r0.w + r1.w + r2.w + r3.w;
            float* p = (float*)&g_agg4[(size_t)node * C4 + t];
            atomicAdd(p + 0, rx); atomicAdd(p + 1, ry);
            atomicAdd(p + 2, rz); atomicAdd(p + 3, rw);
        }
        __syncthreads();
    }
}

// ---------------------------------------------------------------------------
// GEMM: out[N,96] = g_agg @ W + b (optional ReLU); W in smem; 2 rows/warp
// ---------------------------------------------------------------------------
template <bool RELU>
__global__ void __launch_bounds__(256) gemm_kernel(
        const float* __restrict__ W, const float* __restrict__ b,
        float* __restrict__ out, int N) {
    __shared__ float Ws[F * F];
    for (int i = threadIdx.x; i < F * F; i += blockDim.x) Ws[i] = W[i];
    __syncthreads();

    const float* __restrict__ x = (const float*)g_agg4;
    const int lane = threadIdx.x & 31;
    const int warp = threadIdx.x >> 5;
    int row0 = (blockIdx.x * 8 + warp) * 2;
    if (row0 >= N) return;

    float xr[2][3];
#pragma unroll
    for (int r = 0; r < 2; r++) {
        int row = row0 + r;
#pragma unroll
        for (int q = 0; q < 3; q++)
            xr[r][q] = (row < N) ? x[(size_t)row * F + q * 32 + lane] : 0.f;
    }

    float acc[2][3] = {};
#pragma unroll
    for (int q = 0; q < 3; q++) {
#pragma unroll
        for (int kk = 0; kk < 32; kk++) {
            int k = q * 32 + kk;
            float w0 = Ws[k * F + lane];
            float w1 = Ws[k * F + 32 + lane];
            float w2 = Ws[k * F + 64 + lane];
#pragma unroll
            for (int r = 0; r < 2; r++) {
                float xv = __shfl_sync(FULLM, xr[r][q], kk);
                acc[r][0] = fmaf(xv, w0, acc[r][0]);
                acc[r][1] = fmaf(xv, w1, acc[r][1]);
                acc[r][2] = fmaf(xv, w2, acc[r][2]);
            }
        }
    }

#pragma unroll
    for (int r = 0; r < 2; r++) {
        int row = row0 + r;
        if (row < N) {
#pragma unroll
            for (int q = 0; q < 3; q++) {
                float v = acc[r][q] + b[q * 32 + lane];
                if (RELU) v = fmaxf(v, 0.f);
                out[(size_t)row * F + q * 32 + lane] = v;
            }
        }
    }
}

// ---------------------------------------------------------------------------
// inputs: x, W1, b1, W2a, b2a, W2b, b2b, edge_index[2,E]
// output: concat(mu [N,F], logstd [N,F])
// Linearity: GCN(x) = (A_norm @ x) @ W + b -> aggregate first, GEMM second;
// layer-2 GEMMs share one aggregation of h1.
// ---------------------------------------------------------------------------
extern "C" void kernel_launch(void* const* d_in, const int* in_sizes, int n_in,
                              void* d_out, int out_size) {
    const float* x   = (const float*)d_in[0];
    const float* W1  = (const float*)d_in[1];
    const float* b1  = (const float*)d_in[2];
    const float* W2a = (const float*)d_in[3];
    const float* b2a = (const float*)d_in[4];
    const float* W2b = (const float*)d_in[5];
    const float* b2b = (const float*)d_in[6];
    const int*   ei  = (const int*)d_in[7];

    const int N = in_sizes[0] / F;
    const int E = in_sizes[7] / 2;
    const int* src = ei;
    const int* dst = ei + E;
    float* out = (float*)d_out;
    const int NF = N * F;

    const int TB = 256;
    int eg = (E + TB - 1) / TB;
    int gg = (N + 15) / 16;          // gemm grid (8 warps x 2 rows)
    int ag = (N + 3) / 4;            // gather grid (4 nodes/block)

    deg_kernel <<<eg, TB>>>(dst, E);            // launch 0
    scan_kernel<<<1, 1024>>>(N, E);             // launch 1
    fill_kernel<<<eg, TB>>>(src, dst, E);       // launch 2

    gather_kernel<<<ag, 96>>>(x, N);            // launch 3 (profiled)
    heavy_kernel <<<256, 96>>>(x);
    gemm_kernel<true><<<gg, TB>>>(W1, b1, g_h1, N);

    gather_kernel<<<ag, 96>>>(g_h1, N);
    heavy_kernel <<<256, 96>>>(g_h1);
    gemm_kernel<false><<<gg, TB>>>(W2a, b2a, out, N);
    gemm_kernel<false><<<gg, TB>>>(W2b, b2b, out + NF, N);
}

// round 8
// speedup vs baseline: 7.8204x; 7.8204x over previous
#include <cuda_runtime.h>

#define F 96
#define C4 24               // float4 chunks per feature row
#define CAPN 50240          // node capacity (N = 50000)
#define FULLM 0xffffffffu
#define ET 64               // edges per scatter tile

// ---- scratch (__device__ globals; accessed ONLY by name in device code) ----
__device__ int    g_degi[CAPN];        // zeroed statically; re-zeroed each call
__device__ float  g_dinv[CAPN];
__device__ float4 g_xs  [CAPN * C4];   // x pre-scaled by dinv[row]
__device__ float4 g_agg1[CAPN * C4];   // scatter target 1 (zeroed each call)
__device__ float4 g_h1s [CAPN * C4];   // dinv[row] * relu((A x)@W1 + b1)
__device__ float4 g_agg2[CAPN * C4];   // scatter target 2 (zeroed each call)

// device-side buffer selectors (resolved at compile time inside kernels)
template <int SEL> __device__ __forceinline__ float4* buf();
template <> __device__ __forceinline__ float4* buf<0>() { return g_xs;   }
template <> __device__ __forceinline__ float4* buf<1>() { return g_agg1; }
template <> __device__ __forceinline__ float4* buf<2>() { return g_h1s;  }
template <> __device__ __forceinline__ float4* buf<3>() { return g_agg2; }

// 128-bit vector atomic add (cc >= 9.0); p is a true device address
__device__ __forceinline__ void red4(float4* p, float4 v) {
    atomicAdd(p, v);
}

// ---------------------------------------------------------------------------
// launch 0: degree by dst; warp-aggregated for contiguous hub edges
// ---------------------------------------------------------------------------
__global__ void deg_kernel(const int* __restrict__ dst, int E) {
    int e = blockIdx.x * blockDim.x + threadIdx.x;
    bool valid = e < E;
    int d = valid ? dst[e] : -1;
    int d0 = __shfl_sync(FULLM, d, 0);
    unsigned bal = __ballot_sync(FULLM, valid && d == d0);
    if (bal == FULLM) {
        if ((threadIdx.x & 31) == 0) atomicAdd(&g_degi[d0], 32);
    } else if (valid) {
        atomicAdd(&g_degi[d], 1);
    }
}

// ---------------------------------------------------------------------------
// launch 1: dinv + re-zero degi + zero both agg buffers
// ---------------------------------------------------------------------------
__global__ void init_kernel(int N) {
    int i = blockIdx.x * blockDim.x + threadIdx.x;
    int n4 = N * C4;
    float4 z = make_float4(0.f, 0.f, 0.f, 0.f);
    if (i < n4) { g_agg1[i] = z; g_agg2[i] = z; }
    if (i < N) {
        int dg = g_degi[i];
        g_dinv[i] = dg > 0 ? rsqrtf(fmaxf((float)dg, 1.f)) : 0.f;
        g_degi[i] = 0;      // ready for next replay
    }
}

// ---------------------------------------------------------------------------
// launch 2: pre-scale x by dinv[row] -> g_xs  (float4)
// ---------------------------------------------------------------------------
__global__ void xscale_kernel(const float4* __restrict__ x, int N) {
    int i = blockIdx.x * blockDim.x + threadIdx.x;   // float4 index
    int n4 = N * C4;
    if (i < n4) {
        float dv = g_dinv[i / C4];
        float4 v = x[i];
        v.x *= dv; v.y *= dv; v.z *= dv; v.w *= dv;
        g_xs[i] = v;
    }
}

// ---------------------------------------------------------------------------
// Scatter: agg[dst] += feat[src]   (feat already pre-scaled by dinv[src])
// 192 threads = 8 edge-slots x 24 chunks; 64-edge tiles staged in smem.
// Uniform-dst tiles (hub) reduce in registers+smem -> 1 atomic per chunk.
// IN: 0=g_xs, 2=g_h1s.  OUT: 1=g_agg1, 3=g_agg2.
// ---------------------------------------------------------------------------
template <int IN, int OUT>
__global__ void __launch_bounds__(192) scatter_kernel(
        const int* __restrict__ src, const int* __restrict__ dst, int E) {
    const float4* __restrict__ feat = buf<IN>();
    float4* __restrict__ agg = buf<OUT>();

    const int t = threadIdx.x;
    const int c = t % C4;               // chunk 0..23
    const int g = t / C4;               // edge slot 0..7
    __shared__ int    ss[ET], sd[ET];
    __shared__ int    s_uni;
    __shared__ float4 sred[192];

    const int base = blockIdx.x * ET;
    const int m = min(ET, E - base);

    if (t == 0) s_uni = (m == ET) ? 1 : 0;
    if (t < m) { ss[t] = src[base + t]; sd[t] = dst[base + t]; }
    __syncthreads();
    if (t < m && sd[t] != sd[0]) s_uni = 0;
    __syncthreads();

    if (s_uni) {
        // all 64 edges -> same dst: register-accumulate, smem-reduce, 1 atom/chunk
        float4 acc = make_float4(0.f, 0.f, 0.f, 0.f);
#pragma unroll
        for (int r = 0; r < 8; r++) {
            int j = r * 8 + g;
            float4 v = __ldg(feat + (size_t)ss[j] * C4 + c);
            acc.x += v.x; acc.y += v.y; acc.z += v.z; acc.w += v.w;
        }
        sred[t] = acc;
        __syncthreads();
        if (g == 0) {
#pragma unroll
            for (int k = 1; k < 8; k++) {
                float4 v = sred[k * C4 + c];
                acc.x += v.x; acc.y += v.y; acc.z += v.z; acc.w += v.w;
            }
            red4(agg + (size_t)sd[0] * C4 + c, acc);
        }
    } else {
#pragma unroll
        for (int r = 0; r < 8; r++) {
            int j = r * 8 + g;
            if (j < m) {
                float4 v = __ldg(feat + (size_t)ss[j] * C4 + c);
                red4(agg + (size_t)sd[j] * C4 + c, v);
            }
        }
    }
}

// ---------------------------------------------------------------------------
// GEMM: out[N,96] = (agg[row]*dinv[row]) @ W + b
// HID: g_h1s = dinv[row] * relu(.)   (written by name; no host-passed symbol)
// else: writes to `out` (harness pointer).
// IN: 1=g_agg1, 3=g_agg2.
// ---------------------------------------------------------------------------
template <bool HID, int IN>
__global__ void __launch_bounds__(256) gemm_kernel(
        const float* __restrict__ W, const float* __restrict__ b,
        float* __restrict__ out, int N) {
    __shared__ float Ws[F * F];
    for (int i = threadIdx.x; i < F * F; i += blockDim.x) Ws[i] = W[i];
    __syncthreads();

    const float* __restrict__ x = (const float*)buf<IN>();
    float* __restrict__ o = HID ? (float*)g_h1s : out;

    const int lane = threadIdx.x & 31;
    const int warp = threadIdx.x >> 5;
    int row0 = (blockIdx.x * 8 + warp) * 2;
    if (row0 >= N) return;

    float dv[2];
    float xr[2][3];
#pragma unroll
    for (int r = 0; r < 2; r++) {
        int row = row0 + r;
        dv[r] = (row < N) ? g_dinv[row] : 0.f;
#pragma unroll
        for (int q = 0; q < 3; q++)
            xr[r][q] = (row < N) ? x[(size_t)row * F + q * 32 + lane] * dv[r] : 0.f;
    }

    float acc[2][3] = {};
#pragma unroll
    for (int q = 0; q < 3; q++) {
#pragma unroll
        for (int kk = 0; kk < 32; kk++) {
            int k = q * 32 + kk;
            float w0 = Ws[k * F + lane];
            float w1 = Ws[k * F + 32 + lane];
            float w2 = Ws[k * F + 64 + lane];
#pragma unroll
            for (int r = 0; r < 2; r++) {
                float xv = __shfl_sync(FULLM, xr[r][q], kk);
                acc[r][0] = fmaf(xv, w0, acc[r][0]);
                acc[r][1] = fmaf(xv, w1, acc[r][1]);
                acc[r][2] = fmaf(xv, w2, acc[r][2]);
            }
        }
    }

#pragma unroll
    for (int r = 0; r < 2; r++) {
        int row = row0 + r;
        if (row < N) {
#pragma unroll
            for (int q = 0; q < 3; q++) {
                float v = acc[r][q] + b[q * 32 + lane];
                if (HID) v = fmaxf(v, 0.f) * dv[r];
                o[(size_t)row * F + q * 32 + lane] = v;
            }
        }
    }
}

// ---------------------------------------------------------------------------
// inputs: x, W1, b1, W2a, b2a, W2b, b2b, edge_index[2,E]
// output: concat(mu [N,F], logstd [N,F])
//
// A_norm = D^-1/2 A D^-1/2 and GCN linearity give:
//   GCN(x) = (dinv .* (A @ (dinv .* x))) @ W + b
// -> pre-scale features, raw scatter-add over edges, post-scale at GEMM load.
// Layer-2 GEMMs (mu / logstd) share one scatter of h1s.
// NOTE: no __device__ symbol is ever passed from host (ATS shadow-addr trap).
// ---------------------------------------------------------------------------
extern "C" void kernel_launch(void* const* d_in, const int* in_sizes, int n_in,
                              void* d_out, int out_size) {
    const float* x   = (const float*)d_in[0];
    const float* W1  = (const float*)d_in[1];
    const float* b1  = (const float*)d_in[2];
    const float* W2a = (const float*)d_in[3];
    const float* b2a = (const float*)d_in[4];
    const float* W2b = (const float*)d_in[5];
    const float* b2b = (const float*)d_in[6];
    const int*   ei  = (const int*)d_in[7];

    const int N = in_sizes[0] / F;
    const int E = in_sizes[7] / 2;
    const int* src = ei;
    const int* dst = ei + E;
    float* out = (float*)d_out;
    const int NF = N * F;

    const int TB = 256;
    int eg  = (E + TB - 1) / TB;
    int f4g = (N * C4 + TB - 1) / TB;
    int sg  = (E + ET - 1) / ET;
    int gg  = (N + 15) / 16;

    deg_kernel   <<<eg, TB>>>(dst, E);                 // 0
    init_kernel  <<<f4g, TB>>>(N);                     // 1
    xscale_kernel<<<f4g, TB>>>((const float4*)x, N);   // 2
    scatter_kernel<0, 1><<<sg, 192>>>(src, dst, E);    // 3: xs  -> agg1
    gemm_kernel<true, 1> <<<gg, TB>>>(W1, b1, nullptr, N);       // 4: -> h1s
    scatter_kernel<2, 3><<<sg, 192>>>(src, dst, E);    // 5: h1s -> agg2
    gemm_kernel<false, 3><<<gg, TB>>>(W2a, b2a, out, N);         // 6: mu
    gemm_kernel<false, 3><<<gg, TB>>>(W2b, b2b, out + NF, N);    // 7: logstd
}

// round 9
// speedup vs baseline: 7.9183x; 1.0125x over previous
#include <cuda_runtime.h>

#define F 96
#define C4 24               // float4 chunks per feature row
#define CAPN 50240          // node capacity (N = 50000)
#define FULLM 0xffffffffu
#define ET 64               // edges per scatter tile

// ---- scratch (__device__ globals; accessed ONLY by name in device code) ----
__device__ int    g_degi[CAPN];        // zeroed statically; re-zeroed in gemm1
__device__ float  g_dinv[CAPN];
__device__ float4 g_xs  [CAPN * C4];   // x pre-scaled by dinv[row]
__device__ float4 g_agg1[CAPN * C4];   // scatter target 1
__device__ float4 g_h1s [CAPN * C4];   // dinv[row] * relu((A x)@W1 + b1)
__device__ float4 g_agg2[CAPN * C4];   // scatter target 2

template <int SEL> __device__ __forceinline__ float4* buf();
template <> __device__ __forceinline__ float4* buf<0>() { return g_xs;   }
template <> __device__ __forceinline__ float4* buf<1>() { return g_agg1; }
template <> __device__ __forceinline__ float4* buf<2>() { return g_h1s;  }
template <> __device__ __forceinline__ float4* buf<3>() { return g_agg2; }

__device__ __forceinline__ void red4(float4* p, float4 v) { atomicAdd(p, v); }

// ---------------------------------------------------------------------------
// launch 0: degree by dst; warp-aggregated for contiguous hub edges
// ---------------------------------------------------------------------------
__global__ void deg_kernel(const int* __restrict__ dst, int E) {
    int e = blockIdx.x * blockDim.x + threadIdx.x;
    bool valid = e < E;
    int d = valid ? dst[e] : -1;
    int d0 = __shfl_sync(FULLM, d, 0);
    unsigned bal = __ballot_sync(FULLM, valid && d == d0);
    if (bal == FULLM) {
        if ((threadIdx.x & 31) == 0) atomicAdd(&g_degi[d0], 32);
    } else if (valid) {
        atomicAdd(&g_degi[d], 1);
    }
}

// ---------------------------------------------------------------------------
// launch 1: fused init + xscale: dinv from degi, zero aggs, xs = x * dinv
// ---------------------------------------------------------------------------
__global__ void initx_kernel(const float4* __restrict__ x, int N) {
    int i = blockIdx.x * blockDim.x + threadIdx.x;   // float4 index
    int n4 = N * C4;
    if (i >= n4) return;
    int row = i / C4;
    int dg = g_degi[row];
    float dv = dg > 0 ? rsqrtf(fmaxf((float)dg, 1.f)) : 0.f;
    float4 z = make_float4(0.f, 0.f, 0.f, 0.f);
    g_agg1[i] = z;
    g_agg2[i] = z;
    float4 v = x[i];
    v.x *= dv; v.y *= dv; v.z *= dv; v.w *= dv;
    g_xs[i] = v;
    if ((i % C4) == 0) g_dinv[row] = dv;
}

// ---------------------------------------------------------------------------
// Scatter: agg[dst] += feat[src]   (feat already pre-scaled by dinv[src])
// 192 threads = 8 edge-slots x 24 chunks; 64-edge tiles staged in smem.
// Uniform-dst tiles (hub) reduce in registers+smem -> 1 atomic per chunk.
// ---------------------------------------------------------------------------
template <int IN, int OUT>
__global__ void __launch_bounds__(192) scatter_kernel(
        const int* __restrict__ src, const int* __restrict__ dst, int E) {
    const float4* __restrict__ feat = buf<IN>();
    float4* __restrict__ agg = buf<OUT>();

    const int t = threadIdx.x;
    const int c = t % C4;               // chunk 0..23
    const int g = t / C4;               // edge slot 0..7
    __shared__ int    ss[ET], sd[ET];
    __shared__ int    s_uni;
    __shared__ float4 sred[192];

    const int base = blockIdx.x * ET;
    const int m = min(ET, E - base);

    if (t == 0) s_uni = (m == ET) ? 1 : 0;
    if (t < m) { ss[t] = src[base + t]; sd[t] = dst[base + t]; }
    __syncthreads();
    if (t < m && sd[t] != sd[0]) s_uni = 0;
    __syncthreads();

    if (s_uni) {
        float4 acc = make_float4(0.f, 0.f, 0.f, 0.f);
#pragma unroll
        for (int r = 0; r < 8; r++) {
            int j = r * 8 + g;
            float4 v = __ldg(feat + (size_t)ss[j] * C4 + c);
            acc.x += v.x; acc.y += v.y; acc.z += v.z; acc.w += v.w;
        }
        sred[t] = acc;
        __syncthreads();
        if (g == 0) {
#pragma unroll
            for (int k = 1; k < 8; k++) {
                float4 v = sred[k * C4 + c];
                acc.x += v.x; acc.y += v.y; acc.z += v.z; acc.w += v.w;
            }
            red4(agg + (size_t)sd[0] * C4 + c, acc);
        }
    } else {
#pragma unroll
        for (int r = 0; r < 8; r++) {
            int j = r * 8 + g;
            if (j < m) {
                float4 v = __ldg(feat + (size_t)ss[j] * C4 + c);
                red4(agg + (size_t)sd[j] * C4 + c, v);
            }
        }
    }
}

// ---------------------------------------------------------------------------
// GEMM helper: per-warp 2-row x 96-col product against smem weights
// ---------------------------------------------------------------------------
__device__ __forceinline__ void mm2(const float Ws[F * F],
                                    const float xr[2][3],
                                    float acc[2][3], int lane) {
#pragma unroll
    for (int q = 0; q < 3; q++) {
#pragma unroll
        for (int kk = 0; kk < 32; kk++) {
            int k = q * 32 + kk;
            float w0 = Ws[k * F + lane];
            float w1 = Ws[k * F + 32 + lane];
            float w2 = Ws[k * F + 64 + lane];
#pragma unroll
            for (int r = 0; r < 2; r++) {
                float xv = __shfl_sync(FULLM, xr[r][q], kk);
                acc[r][0] = fmaf(xv, w0, acc[r][0]);
                acc[r][1] = fmaf(xv, w1, acc[r][1]);
                acc[r][2] = fmaf(xv, w2, acc[r][2]);
            }
        }
    }
}

// ---------------------------------------------------------------------------
// launch 3: gemm1: g_h1s = dinv .* relu((g_agg1 .* dinv) @ W1 + b1)
// Also re-zeroes g_degi for the next graph replay (idle-lane work).
// ---------------------------------------------------------------------------
__global__ void __launch_bounds__(256) gemm1_kernel(
        const float* __restrict__ W, const float* __restrict__ b, int N) {
    __shared__ float Ws[F * F];
    {   // replay-reset of degree counters, piggybacked
        int gi = blockIdx.x * blockDim.x + threadIdx.x;
        if (gi < N) g_degi[gi] = 0;
    }
    for (int i = threadIdx.x; i < F * F; i += blockDim.x) Ws[i] = W[i];
    __syncthreads();

    const float* __restrict__ x = (const float*)g_agg1;
    float* __restrict__ o = (float*)g_h1s;

    const int lane = threadIdx.x & 31;
    const int warp = threadIdx.x >> 5;
    int row0 = (blockIdx.x * 8 + warp) * 2;
    if (row0 >= N) return;

    float dv[2];
    float xr[2][3];
#pragma unroll
    for (int r = 0; r < 2; r++) {
        int row = row0 + r;
        dv[r] = (row < N) ? g_dinv[row] : 0.f;
#pragma unroll
        for (int q = 0; q < 3; q++)
            xr[r][q] = (row < N) ? x[(size_t)row * F + q * 32 + lane] * dv[r] : 0.f;
    }

    float acc[2][3] = {};
    mm2(Ws, xr, acc, lane);

#pragma unroll
    for (int r = 0; r < 2; r++) {
        int row = row0 + r;
        if (row < N) {
#pragma unroll
            for (int q = 0; q < 3; q++) {
                float v = acc[r][q] + b[q * 32 + lane];
                o[(size_t)row * F + q * 32 + lane] = fmaxf(v, 0.f) * dv[r];
            }
        }
    }
}

// ---------------------------------------------------------------------------
// launch 5: fused dual GEMM: mu = xa@W2a+b2a ; logstd = xa@W2b+b2b
// (xa = g_agg2 .* dinv loaded once; W2a then W2b through same smem)
// ---------------------------------------------------------------------------
__global__ void __launch_bounds__(256) gemm2_kernel(
        const float* __restrict__ Wa, const float* __restrict__ ba,
        const float* __restrict__ Wb, const float* __restrict__ bb,
        float* __restrict__ out, int N) {
    __shared__ float Ws[F * F];
    const float* __restrict__ x = (const float*)g_agg2;

    const int lane = threadIdx.x & 31;
    const int warp = threadIdx.x >> 5;
    int row0 = (blockIdx.x * 8 + warp) * 2;

    float dv[2];
    float xr[2][3];
#pragma unroll
    for (int r = 0; r < 2; r++) {
        int row = row0 + r;
        bool ok = (row0 < N) && (row < N);
        dv[r] = ok ? g_dinv[row] : 0.f;
#pragma unroll
        for (int q = 0; q < 3; q++)
            xr[r][q] = ok ? x[(size_t)row * F + q * 32 + lane] * dv[r] : 0.f;
    }

    // phase A: mu
    for (int i = threadIdx.x; i < F * F; i += blockDim.x) Ws[i] = Wa[i];
    __syncthreads();
    float acca[2][3] = {};
    mm2(Ws, xr, acca, lane);

    // phase B: logstd
    __syncthreads();
    for (int i = threadIdx.x; i < F * F; i += blockDim.x) Ws[i] = Wb[i];
    __syncthreads();
    float accb[2][3] = {};
    mm2(Ws, xr, accb, lane);

    if (row0 >= N) return;
    const size_t NF = (size_t)N * F;
#pragma unroll
    for (int r = 0; r < 2; r++) {
        int row = row0 + r;
        if (row < N) {
#pragma unroll
            for (int q = 0; q < 3; q++) {
                size_t idx = (size_t)row * F + q * 32 + lane;
                out[idx]      = acca[r][q] + ba[q * 32 + lane];
                out[NF + idx] = accb[r][q] + bb[q * 32 + lane];
            }
        }
    }
}

// ---------------------------------------------------------------------------
// inputs: x, W1, b1, W2a, b2a, W2b, b2b, edge_index[2,E]
// output: concat(mu [N,F], logstd [N,F])
//
// A_norm = D^-1/2 A D^-1/2 and GCN linearity give:
//   GCN(x) = (dinv .* (A @ (dinv .* x))) @ W + b
// -> pre-scale features, raw scatter-add over edges, post-scale at GEMM load.
// NOTE: no __device__ symbol is ever passed from host (ATS shadow-addr trap).
// ---------------------------------------------------------------------------
extern "C" void kernel_launch(void* const* d_in, const int* in_sizes, int n_in,
                              void* d_out, int out_size) {
    const float* x   = (const float*)d_in[0];
    const float* W1  = (const float*)d_in[1];
    const float* b1  = (const float*)d_in[2];
    const float* W2a = (const float*)d_in[3];
    const float* b2a = (const float*)d_in[4];
    const float* W2b = (const float*)d_in[5];
    const float* b2b = (const float*)d_in[6];
    const int*   ei  = (const int*)d_in[7];

    const int N = in_sizes[0] / F;
    const int E = in_sizes[7] / 2;
    const int* src = ei;
    const int* dst = ei + E;
    float* out = (float*)d_out;

    const int TB = 256;
    int eg  = (E + TB - 1) / TB;
    int f4g = (N * C4 + TB - 1) / TB;
    int sg  = (E + ET - 1) / ET;
    int gg  = (N + 15) / 16;

    deg_kernel  <<<eg, TB>>>(dst, E);                    // 0
    initx_kernel<<<f4g, TB>>>((const float4*)x, N);      // 1
    scatter_kernel<0, 1><<<sg, 192>>>(src, dst, E);      // 2: xs  -> agg1
    gemm1_kernel<<<gg, TB>>>(W1, b1, N);                 // 3: -> h1s (+deg reset)
    scatter_kernel<2, 3><<<sg, 192>>>(src, dst, E);      // 4: h1s -> agg2
    gemm2_kernel<<<gg, TB>>>(W2a, b2a, W2b, b2b, out, N);// 5: mu + logstd
}

// round 10
// speedup vs baseline: 7.9783x; 1.0076x over previous
#include <cuda_runtime.h>

#define F 96
#define C4 24               // float4 chunks per feature row
#define CAPN 50240          // node capacity (N = 50000)
#define FULLM 0xffffffffu
#define ET 64               // edges per scatter tile
#define WPAD 100            // padded k-stride for transposed W in smem

// ---- scratch (__device__ globals; accessed ONLY by name in device code) ----
__device__ int    g_degi[CAPN];        // zeroed statically; re-zeroed in gemm1
__device__ float  g_dinv[CAPN];
__device__ float4 g_xs  [CAPN * C4];   // x pre-scaled by dinv[row]
__device__ float4 g_agg1[CAPN * C4];   // scatter target 1
__device__ float4 g_h1s [CAPN * C4];   // dinv[row] * relu((A x)@W1 + b1)
__device__ float4 g_agg2[CAPN * C4];   // scatter target 2

template <int SEL> __device__ __forceinline__ float4* buf();
template <> __device__ __forceinline__ float4* buf<0>() { return g_xs;   }
template <> __device__ __forceinline__ float4* buf<1>() { return g_agg1; }
template <> __device__ __forceinline__ float4* buf<2>() { return g_h1s;  }
template <> __device__ __forceinline__ float4* buf<3>() { return g_agg2; }

__device__ __forceinline__ void red4(float4* p, float4 v) { atomicAdd(p, v); }

// packed f32x2 fma: a += v * m  (lanes independent)
__device__ __forceinline__ void fma2(unsigned long long& a,
                                     unsigned long long v,
                                     unsigned long long m) {
    asm volatile("fma.rn.f32x2 %0, %1, %2, %0;" : "+l"(a) : "l"(v), "l"(m));
}
__device__ __forceinline__ float sum2(unsigned long long a) {
    float2 f = *reinterpret_cast<float2*>(&a);
    return f.x + f.y;
}

// ---------------------------------------------------------------------------
// launch 0: degree by dst; warp-aggregated for contiguous hub edges
// ---------------------------------------------------------------------------
__global__ void deg_kernel(const int* __restrict__ dst, int E) {
    int e = blockIdx.x * blockDim.x + threadIdx.x;
    bool valid = e < E;
    int d = valid ? dst[e] : -1;
    int d0 = __shfl_sync(FULLM, d, 0);
    unsigned bal = __ballot_sync(FULLM, valid && d == d0);
    if (bal == FULLM) {
        if ((threadIdx.x & 31) == 0) atomicAdd(&g_degi[d0], 32);
    } else if (valid) {
        atomicAdd(&g_degi[d], 1);
    }
}

// ---------------------------------------------------------------------------
// launch 1: fused init + xscale: dinv from degi, zero aggs, xs = x * dinv
// ---------------------------------------------------------------------------
__global__ void initx_kernel(const float4* __restrict__ x, int N) {
    int i = blockIdx.x * blockDim.x + threadIdx.x;   // float4 index
    int n4 = N * C4;
    if (i >= n4) return;
    int row = i / C4;
    int dg = g_degi[row];
    float dv = dg > 0 ? rsqrtf(fmaxf((float)dg, 1.f)) : 0.f;
    float4 z = make_float4(0.f, 0.f, 0.f, 0.f);
    g_agg1[i] = z;
    g_agg2[i] = z;
    float4 v = x[i];
    v.x *= dv; v.y *= dv; v.z *= dv; v.w *= dv;
    g_xs[i] = v;
    if ((i % C4) == 0) g_dinv[row] = dv;
}

// ---------------------------------------------------------------------------
// Scatter: agg[dst] += feat[src]   (feat already pre-scaled by dinv[src])
// 192 threads = 8 edge-slots x 24 chunks; 64-edge tiles staged in smem.
// Uniform-dst tiles (hub) reduce in registers+smem -> 1 atomic per chunk.
// ---------------------------------------------------------------------------
template <int IN, int OUT>
__global__ void __launch_bounds__(192) scatter_kernel(
        const int* __restrict__ src, const int* __restrict__ dst, int E) {
    const float4* __restrict__ feat = buf<IN>();
    float4* __restrict__ agg = buf<OUT>();

    const int t = threadIdx.x;
    const int c = t % C4;               // chunk 0..23
    const int g = t / C4;               // edge slot 0..7
    __shared__ int    ss[ET], sd[ET];
    __shared__ int    s_uni;
    __shared__ float4 sred[192];

    const int base = blockIdx.x * ET;
    const int m = min(ET, E - base);

    if (t == 0) s_uni = (m == ET) ? 1 : 0;
    if (t < m) { ss[t] = src[base + t]; sd[t] = dst[base + t]; }
    __syncthreads();
    if (t < m && sd[t] != sd[0]) s_uni = 0;
    __syncthreads();

    if (s_uni) {
        float4 acc = make_float4(0.f, 0.f, 0.f, 0.f);
#pragma unroll
        for (int r = 0; r < 8; r++) {
            int j = r * 8 + g;
            float4 v = __ldg(feat + (size_t)ss[j] * C4 + c);
            acc.x += v.x; acc.y += v.y; acc.z += v.z; acc.w += v.w;
        }
        sred[t] = acc;
        __syncthreads();
        if (g == 0) {
#pragma unroll
            for (int k = 1; k < 8; k++) {
                float4 v = sred[k * C4 + c];
                acc.x += v.x; acc.y += v.y; acc.z += v.z; acc.w += v.w;
            }
            red4(agg + (size_t)sd[0] * C4 + c, acc);
        }
    } else {
#pragma unroll
        for (int r = 0; r < 8; r++) {
            int j = r * 8 + g;
            if (j < m) {
                float4 v = __ldg(feat + (size_t)ss[j] * C4 + c);
                red4(agg + (size_t)sd[j] * C4 + c, v);
            }
        }
    }
}

// ---------------------------------------------------------------------------
// GEMM building blocks (16 rows/block, 8 warps, 2 rows/warp, 3 cols/lane)
// Wt in smem transposed [col][k] (pad WPAD) -> LDS.128 per 4k per col.
// x tile in smem row-major -> broadcast LDS.128 per 4k per row.
// Accumulators packed over k-parity with fma.rn.f32x2.
// ---------------------------------------------------------------------------
__device__ __forceinline__ void load_wt(float* Wt, const float* __restrict__ W,
                                        int t) {
    for (int i = t; i < F * F; i += 256) {
        int k = i / F, c = i % F;
        Wt[c * WPAD + k] = W[i];
    }
}

// compute 2 rows x 3 cols into acc[2][3] (packed)
__device__ __forceinline__ void mmkern(const float* Wt, const float* xs,
                                       int lane, int r0,
                                       unsigned long long acc[2][3]) {
#pragma unroll
    for (int k0 = 0; k0 < F; k0 += 4) {
        ulonglong2 xa = *(const ulonglong2*)&xs[r0 * F + k0];
        ulonglong2 xb = *(const ulonglong2*)&xs[(r0 + 1) * F + k0];
        ulonglong2 w0 = *(const ulonglong2*)&Wt[lane * WPAD + k0];
        ulonglong2 w1 = *(const ulonglong2*)&Wt[(lane + 32) * WPAD + k0];
        ulonglong2 w2 = *(const ulonglong2*)&Wt[(lane + 64) * WPAD + k0];
        fma2(acc[0][0], xa.x, w0.x); fma2(acc[0][0], xa.y, w0.y);
        fma2(acc[0][1], xa.x, w1.x); fma2(acc[0][1], xa.y, w1.y);
        fma2(acc[0][2], xa.x, w2.x); fma2(acc[0][2], xa.y, w2.y);
        fma2(acc[1][0], xb.x, w0.x); fma2(acc[1][0], xb.y, w0.y);
        fma2(acc[1][1], xb.x, w1.x); fma2(acc[1][1], xb.y, w1.y);
        fma2(acc[1][2], xb.x, w2.x); fma2(acc[1][2], xb.y, w2.y);
    }
}

// load 16-row x tile (scaled by dinv) from agg buffer into smem
template <int IN>
__device__ __forceinline__ void load_xtile(float* xs, int row0, int N, int t) {
    const float4* __restrict__ a = buf<IN>();
    for (int i = t; i < 16 * C4; i += 256) {     // float4 index within tile
        int r = i / C4, c4 = i % C4;
        int row = row0 + r;
        float4 v = make_float4(0.f, 0.f, 0.f, 0.f);
        if (row < N) {
            float dv = g_dinv[row];
            v = a[(size_t)row * C4 + c4];
            v.x *= dv; v.y *= dv; v.z *= dv; v.w *= dv;
        }
        ((float4*)xs)[i] = v;
    }
}

// ---------------------------------------------------------------------------
// launch 3: gemm1: g_h1s = dinv .* relu((g_agg1 .* dinv) @ W1 + b1)
// Also re-zeroes g_degi for the next graph replay.
// ---------------------------------------------------------------------------
__global__ void __launch_bounds__(256) gemm1_kernel(
        const float* __restrict__ W, const float* __restrict__ b, int N) {
    __shared__ __align__(16) float Wt[F * WPAD];
    __shared__ __align__(16) float xs[16 * F];
    const int t = threadIdx.x;
    {   // replay-reset of degree counters, piggybacked
        int gi = blockIdx.x * 256 + t;
        if (gi < N) g_degi[gi] = 0;
    }
    const int row0 = blockIdx.x * 16;
    load_wt(Wt, W, t);
    load_xtile<1>(xs, row0, N, t);
    __syncthreads();

    const int lane = t & 31;
    const int warp = t >> 5;
    unsigned long long acc[2][3] = {};
    mmkern(Wt, xs, lane, warp * 2, acc);

#pragma unroll
    for (int r = 0; r < 2; r++) {
        int row = row0 + warp * 2 + r;
        if (row < N) {
            float dv = g_dinv[row];
            float* o = (float*)g_h1s + (size_t)row * F;
#pragma unroll
            for (int q = 0; q < 3; q++) {
                float v = sum2(acc[r][q]) + b[q * 32 + lane];
                o[q * 32 + lane] = fmaxf(v, 0.f) * dv;
            }
        }
    }
}

// ---------------------------------------------------------------------------
// launch 5: fused dual GEMM: mu = xa@W2a+b2a ; logstd = xa@W2b+b2b
// xa = g_agg2 .* dinv loaded once; Wa then Wb through the same smem buffer.
// ---------------------------------------------------------------------------
__global__ void __launch_bounds__(256) gemm2_kernel(
        const float* __restrict__ Wa, const float* __restrict__ ba,
        const float* __restrict__ Wb, const float* __restrict__ bb,
        float* __restrict__ out, int N) {
    __shared__ __align__(16) float Wt[F * WPAD];
    __shared__ __align__(16) float xs[16 * F];
    const int t = threadIdx.x;
    const int row0 = blockIdx.x * 16;
    load_wt(Wt, Wa, t);
    load_xtile<3>(xs, row0, N, t);
    __syncthreads();

    const int lane = t & 31;
    const int warp = t >> 5;
    unsigned long long acca[2][3] = {};
    mmkern(Wt, xs, lane, warp * 2, acca);

    __syncthreads();                 // all reads of Wa done
    load_wt(Wt, Wb, t);
    __syncthreads();
    unsigned long long accb[2][3] = {};
    mmkern(Wt, xs, lane, warp * 2, accb);

    const size_t NF = (size_t)N * F;
#pragma unroll
    for (int r = 0; r < 2; r++) {
        int row = row0 + warp * 2 + r;
        if (row < N) {
            size_t o = (size_t)row * F;
#pragma unroll
            for (int q = 0; q < 3; q++) {
                int col = q * 32 + lane;
                out[o + col]      = sum2(acca[r][q]) + ba[col];
                out[NF + o + col] = sum2(accb[r][q]) + bb[col];
            }
        }
    }
}

// ---------------------------------------------------------------------------
// inputs: x, W1, b1, W2a, b2a, W2b, b2b, edge_index[2,E]
// output: concat(mu [N,F], logstd [N,F])
//
// A_norm = D^-1/2 A D^-1/2 and GCN linearity give:
//   GCN(x) = (dinv .* (A @ (dinv .* x))) @ W + b
// -> pre-scale features, raw scatter-add over edges, post-scale at GEMM load.
// NOTE: no __device__ symbol is ever passed from host (ATS shadow-addr trap).
// ---------------------------------------------------------------------------
extern "C" void kernel_launch(void* const* d_in, const int* in_sizes, int n_in,
                              void* d_out, int out_size) {
    const float* x   = (const float*)d_in[0];
    const float* W1  = (const float*)d_in[1];
    const float* b1  = (const float*)d_in[2];
    const float* W2a = (const float*)d_in[3];
    const float* b2a = (const float*)d_in[4];
    const float* W2b = (const float*)d_in[5];
    const float* b2b = (const float*)d_in[6];
    const int*   ei  = (const int*)d_in[7];

    const int N = in_sizes[0] / F;
    const int E = in_sizes[7] / 2;
    const int* src = ei;
    const int* dst = ei + E;
    float* out = (float*)d_out;

    const int TB = 256;
    int eg  = (E + TB - 1) / TB;
    int f4g = (N * C4 + TB - 1) / TB;
    int sg  = (E + ET - 1) / ET;
    int gg  = (N + 15) / 16;

    deg_kernel  <<<eg, TB>>>(dst, E);                    // 0
    initx_kernel<<<f4g, TB>>>((const float4*)x, N);      // 1
    scatter_kernel<0, 1><<<sg, 192>>>(src, dst, E);      // 2: xs  -> agg1
    gemm1_kernel<<<gg, TB>>>(W1, b1, N);                 // 3: -> h1s (+deg reset)
    scatter_kernel<2, 3><<<sg, 192>>>(src, dst, E);      // 4: h1s -> agg2
    gemm2_kernel<<<gg, TB>>>(W2a, b2a, W2b, b2b, out, N);// 5: mu + logstd
}

// round 11
// speedup vs baseline: 8.2035x; 1.0282x over previous
#include <cuda_runtime.h>

#define F 96
#define C4 24               // float4 chunks per feature row
#define CAPN 50240          // node capacity (N = 50000)
#define FULLM 0xffffffffu
#define ET 64               // edges per scatter tile
#define WPAD 100            // padded k-stride for transposed W in smem
#define XPAD 100            // padded k-stride for x tile in smem

// ---- scratch (__device__ globals; accessed ONLY by name in device code) ----
__device__ int    g_degi[CAPN];        // zeroed statically; re-zeroed in gemm1
__device__ float  g_dinv[CAPN];
__device__ float4 g_xs  [CAPN * C4];   // x pre-scaled by dinv[row]
__device__ float4 g_agg1[CAPN * C4];   // scatter target 1
__device__ float4 g_h1s [CAPN * C4];   // dinv[row] * relu((A x)@W1 + b1)
__device__ float4 g_agg2[CAPN * C4];   // scatter target 2

template <int SEL> __device__ __forceinline__ float4* buf();
template <> __device__ __forceinline__ float4* buf<0>() { return g_xs;   }
template <> __device__ __forceinline__ float4* buf<1>() { return g_agg1; }
template <> __device__ __forceinline__ float4* buf<2>() { return g_h1s;  }
template <> __device__ __forceinline__ float4* buf<3>() { return g_agg2; }

__device__ __forceinline__ void red4(float4* p, float4 v) { atomicAdd(p, v); }

// packed f32x2 fma: a += v * m  (lanes independent)
__device__ __forceinline__ void fma2(unsigned long long& a,
                                     unsigned long long v,
                                     unsigned long long m) {
    asm volatile("fma.rn.f32x2 %0, %1, %2, %0;" : "+l"(a) : "l"(v), "l"(m));
}
__device__ __forceinline__ float sum2(unsigned long long a) {
    float2 f = *reinterpret_cast<float2*>(&a);
    return f.x + f.y;
}

// ---------------------------------------------------------------------------
// launch 0: degree by dst; warp-aggregated for contiguous hub edges
// ---------------------------------------------------------------------------
__global__ void deg_kernel(const int* __restrict__ dst, int E) {
    int e = blockIdx.x * blockDim.x + threadIdx.x;
    bool valid = e < E;
    int d = valid ? dst[e] : -1;
    int d0 = __shfl_sync(FULLM, d, 0);
    unsigned bal = __ballot_sync(FULLM, valid && d == d0);
    if (bal == FULLM) {
        if ((threadIdx.x & 31) == 0) atomicAdd(&g_degi[d0], 32);
    } else if (valid) {
        atomicAdd(&g_degi[d], 1);
    }
}

// ---------------------------------------------------------------------------
// launch 1: fused init + xscale: dinv from degi, zero aggs, xs = x * dinv
// ---------------------------------------------------------------------------
__global__ void initx_kernel(const float4* __restrict__ x, int N) {
    int i = blockIdx.x * blockDim.x + threadIdx.x;   // float4 index
    int n4 = N * C4;
    if (i >= n4) return;
    int row = i / C4;
    int dg = g_degi[row];
    float dv = dg > 0 ? rsqrtf(fmaxf((float)dg, 1.f)) : 0.f;
    float4 z = make_float4(0.f, 0.f, 0.f, 0.f);
    g_agg1[i] = z;
    g_agg2[i] = z;
    float4 v = x[i];
    v.x *= dv; v.y *= dv; v.z *= dv; v.w *= dv;
    g_xs[i] = v;
    if ((i % C4) == 0) g_dinv[row] = dv;
}

// ---------------------------------------------------------------------------
// Scatter: agg[dst] += feat[src]   (feat already pre-scaled by dinv[src])
// 192 threads = 8 edge-slots x 24 chunks; 64-edge tiles staged in smem.
// Uniform-dst tiles (hub) reduce in registers+smem -> 1 atomic per chunk.
// ---------------------------------------------------------------------------
template <int IN, int OUT>
__global__ void __launch_bounds__(192) scatter_kernel(
        const int* __restrict__ src, const int* __restrict__ dst, int E) {
    const float4* __restrict__ feat = buf<IN>();
    float4* __restrict__ agg = buf<OUT>();

    const int t = threadIdx.x;
    const int c = t % C4;               // chunk 0..23
    const int g = t / C4;               // edge slot 0..7
    __shared__ int    ss[ET], sd[ET];
    __shared__ int    s_uni;
    __shared__ float4 sred[192];

    const int base = blockIdx.x * ET;
    const int m = min(ET, E - base);

    if (t == 0) s_uni = (m == ET) ? 1 : 0;
    if (t < m) { ss[t] = src[base + t]; sd[t] = dst[base + t]; }
    __syncthreads();
    if (t < m && sd[t] != sd[0]) s_uni = 0;
    __syncthreads();

    if (s_uni) {
        float4 acc = make_float4(0.f, 0.f, 0.f, 0.f);
#pragma unroll
        for (int r = 0; r < 8; r++) {
            int j = r * 8 + g;
            float4 v = __ldg(feat + (size_t)ss[j] * C4 + c);
            acc.x += v.x; acc.y += v.y; acc.z += v.z; acc.w += v.w;
        }
        sred[t] = acc;
        __syncthreads();
        if (g == 0) {
#pragma unroll
            for (int k = 1; k < 8; k++) {
                float4 v = sred[k * C4 + c];
                acc.x += v.x; acc.y += v.y; acc.z += v.z; acc.w += v.w;
            }
            red4(agg + (size_t)sd[0] * C4 + c, acc);
        }
    } else {
#pragma unroll
        for (int r = 0; r < 8; r++) {
            int j = r * 8 + g;
            if (j < m) {
                float4 v = __ldg(feat + (size_t)ss[j] * C4 + c);
                red4(agg + (size_t)sd[j] * C4 + c, v);
            }
        }
    }
}

// ---------------------------------------------------------------------------
// GEMM building blocks.
// Block = 32 rows, 8 warps; warp owns 12 columns; lane = row.
// Wt in smem transposed [col][k] -> BROADCAST LDS.128 per col per 4k (16B).
// xs in smem [row][k] (pad XPAD, 16B-unit stride 25 = odd -> conflict-free).
// ---------------------------------------------------------------------------
__device__ __forceinline__ void load_wt(float* Wt, const float* __restrict__ W,
                                        int t) {
    for (int i = t; i < F * F; i += 256) {
        int k = i / F, c = i % F;
        Wt[c * WPAD + k] = W[i];
    }
}

// load 32-row x tile (scaled by dinv) from agg buffer into smem [row][k]
template <int IN>
__device__ __forceinline__ void load_xtile(float* xs, int row0, int N, int t) {
    const float4* __restrict__ a = buf<IN>();
    for (int i = t; i < 32 * C4; i += 256) {     // float4 index within tile
        int r = i / C4, c4 = i % C4;
        int row = row0 + r;
        float4 v = make_float4(0.f, 0.f, 0.f, 0.f);
        if (row < N) {
            float dv = g_dinv[row];
            v = a[(size_t)row * C4 + c4];
            v.x *= dv; v.y *= dv; v.z *= dv; v.w *= dv;
        }
        *(float4*)&xs[r * XPAD + c4 * 4] = v;
    }
}

// one row (lane) x 12 cols (warp) product, packed over k-parity
__device__ __forceinline__ void mmkern(const float* Wt, const float* xs,
                                       int lane, int col0,
                                       unsigned long long acc[12]) {
#pragma unroll 4
    for (int k0 = 0; k0 < F; k0 += 4) {
        ulonglong2 xv = *(const ulonglong2*)&xs[lane * XPAD + k0];
#pragma unroll
        for (int c = 0; c < 12; c++) {
            ulonglong2 wv = *(const ulonglong2*)&Wt[(col0 + c) * WPAD + k0];
            fma2(acc[c], xv.x, wv.x);
            fma2(acc[c], xv.y, wv.y);
        }
    }
}

// ---------------------------------------------------------------------------
// launch 3: gemm1: g_h1s = dinv .* relu((g_agg1 .* dinv) @ W1 + b1)
// Also re-zeroes g_degi for the next graph replay.
// ---------------------------------------------------------------------------
__global__ void __launch_bounds__(256) gemm1_kernel(
        const float* __restrict__ W, const float* __restrict__ b, int N) {
    __shared__ __align__(16) float Wt[F * WPAD];
    __shared__ __align__(16) float xs[32 * XPAD];
    const int t = threadIdx.x;
    {   // replay-reset of degree counters, piggybacked
        int gi = blockIdx.x * 256 + t;
        if (gi < N) g_degi[gi] = 0;
    }
    const int row0 = blockIdx.x * 32;
    load_wt(Wt, W, t);
    load_xtile<1>(xs, row0, N, t);
    __syncthreads();

    const int lane = t & 31;
    const int col0 = (t >> 5) * 12;
    unsigned long long acc[12] = {};
    mmkern(Wt, xs, lane, col0, acc);

    int row = row0 + lane;
    if (row < N) {
        float dv = g_dinv[row];
        float* o = (float*)g_h1s + (size_t)row * F + col0;
#pragma unroll
        for (int q = 0; q < 3; q++) {
            float4 r;
            r.x = fmaxf(sum2(acc[q*4+0]) + b[col0 + q*4 + 0], 0.f) * dv;
            r.y = fmaxf(sum2(acc[q*4+1]) + b[col0 + q*4 + 1], 0.f) * dv;
            r.z = fmaxf(sum2(acc[q*4+2]) + b[col0 + q*4 + 2], 0.f) * dv;
            r.w = fmaxf(sum2(acc[q*4+3]) + b[col0 + q*4 + 3], 0.f) * dv;
            *(float4*)&o[q * 4] = r;
        }
    }
}

// ---------------------------------------------------------------------------
// launch 5: fused dual GEMM: mu = xa@W2a+b2a ; logstd = xa@W2b+b2b
// xa = g_agg2 .* dinv loaded once; Wa then Wb through the same smem buffer.
// ---------------------------------------------------------------------------
__global__ void __launch_bounds__(256) gemm2_kernel(
        const float* __restrict__ Wa, const float* __restrict__ ba,
        const float* __restrict__ Wb, const float* __restrict__ bb,
        float* __restrict__ out, int N) {
    __shared__ __align__(16) float Wt[F * WPAD];
    __shared__ __align__(16) float xs[32 * XPAD];
    const int t = threadIdx.x;
    const int row0 = blockIdx.x * 32;
    load_wt(Wt, Wa, t);
    load_xtile<3>(xs, row0, N, t);
    __syncthreads();

    const int lane = t & 31;
    const int col0 = (t >> 5) * 12;

    unsigned long long acca[12] = {};
    mmkern(Wt, xs, lane, col0, acca);

    __syncthreads();                 // all reads of Wa done
    load_wt(Wt, Wb, t);
    __syncthreads();
    unsigned long long accb[12] = {};
    mmkern(Wt, xs, lane, col0, accb);

    int row = row0 + lane;
    if (row < N) {
        const size_t NF = (size_t)N * F;
        size_t o = (size_t)row * F + col0;
#pragma unroll
        for (int q = 0; q < 3; q++) {
            float4 ra, rb;
            ra.x = sum2(acca[q*4+0]) + ba[col0 + q*4 + 0];
            ra.y = sum2(acca[q*4+1]) + ba[col0 + q*4 + 1];
            ra.z = sum2(acca[q*4+2]) + ba[col0 + q*4 + 2];
            ra.w = sum2(acca[q*4+3]) + ba[col0 + q*4 + 3];
            rb.x = sum2(accb[q*4+0]) + bb[col0 + q*4 + 0];
            rb.y = sum2(accb[q*4+1]) + bb[col0 + q*4 + 1];
            rb.z = sum2(accb[q*4+2]) + bb[col0 + q*4 + 2];
            rb.w = sum2(accb[q*4+3]) + bb[col0 + q*4 + 3];
            *(float4*)&out[o + q * 4]      = ra;
            *(float4*)&out[NF + o + q * 4] = rb;
        }
    }
}

// ---------------------------------------------------------------------------
// inputs: x, W1, b1, W2a, b2a, W2b, b2b, edge_index[2,E]
// output: concat(mu [N,F], logstd [N,F])
//
// A_norm = D^-1/2 A D^-1/2 and GCN linearity give:
//   GCN(x) = (dinv .* (A @ (dinv .* x))) @ W + b
// -> pre-scale features, raw scatter-add over edges, post-scale at GEMM load.
// NOTE: no __device__ symbol is ever passed from host (ATS shadow-addr trap).
// ---------------------------------------------------------------------------
extern "C" void kernel_launch(void* const* d_in, const int* in_sizes, int n_in,
                              void* d_out, int out_size) {
    const float* x   = (const float*)d_in[0];
    const float* W1  = (const float*)d_in[1];
    const float* b1  = (const float*)d_in[2];
    const float* W2a = (const float*)d_in[3];
    const float* b2a = (const float*)d_in[4];
    const float* W2b = (const float*)d_in[5];
    const float* b2b = (const float*)d_in[6];
    const int*   ei  = (const int*)d_in[7];

    const int N = in_sizes[0] / F;
    const int E = in_sizes[7] / 2;
    const int* src = ei;
    const int* dst = ei + E;
    float* out = (float*)d_out;

    const int TB = 256;
    int eg  = (E + TB - 1) / TB;
    int f4g = (N * C4 + TB - 1) / TB;
    int sg  = (E + ET - 1) / ET;
    int gg  = (N + 31) / 32;

    deg_kernel  <<<eg, TB>>>(dst, E);                    // 0
    initx_kernel<<<f4g, TB>>>((const float4*)x, N);      // 1
    scatter_kernel<0, 1><<<sg, 192>>>(src, dst, E);      // 2: xs  -> agg1
    gemm1_kernel<<<gg, TB>>>(W1, b1, N);                 // 3: -> h1s (+deg reset)
    scatter_kernel<2, 3><<<sg, 192>>>(src, dst, E);      // 4: h1s -> agg2
    gemm2_kernel<<<gg, TB>>>(W2a, b2a, W2b, b2b, out, N);// 5: mu + logstd
}